// round 16
// baseline (speedup 1.0000x reference)
#include <cuda_runtime.h>
#include <cuda_bf16.h>
#include <math.h>
#include <cstdint>

// ---------------- problem constants ----------------
#define EMB        300
#define C4         75
#define NLAYERS    5
#define NGRAPH     4096
#define ATOM_F     9
#define ATOM_V     128
#define BOND_V     8
#define BN_EPS     1e-5f
#define NMAX       100000
#define EMAX       250000
#define KP1        320
#define KP2        608

// ---------------- device scratch ----------------
__device__ __align__(16) float g_h     [(size_t)NMAX * EMB];
__device__ __align__(16) float g_agg   [(size_t)NMAX * EMB];
__device__ __align__(16) float g_vn    [(size_t)NGRAPH * EMB];
__device__ __align__(16) float g_pooled[(size_t)NGRAPH * EMB];
__device__            float g_counts[NGRAPH];
__device__ __align__(16) __nv_bfloat16 g_agg_h[(size_t)NMAX * KP1];
__device__ __align__(16) __nv_bfloat16 g_agg_l[(size_t)NMAX * KP1];
__device__ __align__(16) __nv_bfloat16 g_t1_h [(size_t)NMAX * KP2];
__device__ __align__(16) __nv_bfloat16 g_t1_l [(size_t)NMAX * KP2];
__device__ __align__(16) __nv_bfloat16 g_pl_h [(size_t)NGRAPH * KP1];
__device__ __align__(16) __nv_bfloat16 g_pl_l [(size_t)NGRAPH * KP1];
__device__ __align__(16) __nv_bfloat16 g_vnt_h[(size_t)NGRAPH * KP2];
__device__ __align__(16) __nv_bfloat16 g_vnt_l[(size_t)NGRAPH * KP2];
__device__ __align__(16) __nv_bfloat16 g_w1t_h[(size_t)NLAYERS * 2 * EMB * KP1];
__device__ __align__(16) __nv_bfloat16 g_w1t_l[(size_t)NLAYERS * 2 * EMB * KP1];
__device__ __align__(16) __nv_bfloat16 g_w2t_h[(size_t)NLAYERS * EMB * KP2];
__device__ __align__(16) __nv_bfloat16 g_w2t_l[(size_t)NLAYERS * EMB * KP2];
__device__ __align__(16) __nv_bfloat16 g_wv1_h[(size_t)(NLAYERS - 1) * 2 * EMB * KP1];
__device__ __align__(16) __nv_bfloat16 g_wv1_l[(size_t)(NLAYERS - 1) * 2 * EMB * KP1];
__device__ __align__(16) __nv_bfloat16 g_wv2_h[(size_t)(NLAYERS - 1) * EMB * KP2];
__device__ __align__(16) __nv_bfloat16 g_wv2_l[(size_t)(NLAYERS - 1) * EMB * KP2];

__device__ __forceinline__ uint32_t smem_u32(const void* p) {
    uint32_t a;
    asm("{ .reg .u64 t; cvta.to.shared.u64 t, %1; cvt.u32.u64 %0, t; }" : "=r"(a) : "l"(p));
    return a;
}

#define LDSM4(r, a) asm volatile( \
    "ldmatrix.sync.aligned.m8n8.x4.shared.b16 {%0,%1,%2,%3},[%4];" \
    : "=r"((r)[0]),"=r"((r)[1]),"=r"((r)[2]),"=r"((r)[3]) : "r"(a))
#define MMA16816(c, a, b) asm volatile( \
    "mma.sync.aligned.m16n8k16.row.col.f32.bf16.bf16.f32 " \
    "{%0,%1,%2,%3},{%4,%5,%6,%7},{%8,%9},{%0,%1,%2,%3};" \
    : "+f"((c)[0]),"+f"((c)[1]),"+f"((c)[2]),"+f"((c)[3]) \
    : "r"((a)[0]),"r"((a)[1]),"r"((a)[2]),"r"((a)[3]),"r"((b)[0]),"r"((b)[1]))
#define CP_ASYNC16(saddr, gptr, ssz) asm volatile( \
    "cp.async.cg.shared.global [%0], [%1], 16, %2;" \
    :: "r"(saddr), "l"(gptr), "r"(ssz))
#define CP_COMMIT() asm volatile("cp.async.commit_group;" ::: "memory")
#define CP_WAIT0()  asm volatile("cp.async.wait_group 0;" ::: "memory")
#define REDV4(p, a, b, c, d) asm volatile( \
    "red.global.add.v4.f32 [%0], {%1,%2,%3,%4};" \
    :: "l"(p), "f"(a), "f"(b), "f"(c), "f"(d) : "memory")
#define REDV2(p, a, b) asm volatile( \
    "red.global.add.v2.f32 [%0], {%1,%2};" \
    :: "l"(p), "f"(a), "f"(b) : "memory")

// ---------------- atom encoder ----------------
__global__ void k_atom_encode(const int* __restrict__ x, const float* __restrict__ atom_emb,
                              float* __restrict__ h, int N) {
    int idx = blockIdx.x * blockDim.x + threadIdx.x;
    if (idx >= N * C4) return;
    int n = idx / C4, c = idx % C4;
    float4 acc = make_float4(0.f, 0.f, 0.f, 0.f);
#pragma unroll
    for (int f = 0; f < ATOM_F; f++) {
        int a = x[n * ATOM_F + f];
        float4 v = *(const float4*)(atom_emb + ((size_t)(f * ATOM_V + a)) * EMB + c * 4);
        acc.x += v.x; acc.y += v.y; acc.z += v.z; acc.w += v.w;
    }
    *(float4*)(h + (size_t)n * EMB + c * 4) = acc;
}

// vn_init also initializes pooled (= vn)
__global__ void k_vn_init(const float* __restrict__ vn_emb, float* __restrict__ vn,
                          float* __restrict__ pooled) {
    int idx = blockIdx.x * blockDim.x + threadIdx.x;
    if (idx >= NGRAPH * EMB) return;
    float v = vn_emb[idx % EMB];
    vn[idx] = v;
    pooled[idx] = v;
}

// ---------------- layer-0 only: h += vn_emb (uniform); agg=(1+eps0)h; pooled += h ----------------
__global__ void k_vnadd0(float* __restrict__ h, float* __restrict__ agg,
                         const float* __restrict__ vn_emb, const int* __restrict__ batch,
                         float* __restrict__ pooled, const float* __restrict__ gin_eps, int N) {
    int idx = blockIdx.x * blockDim.x + threadIdx.x;
    if (idx >= N * C4) return;
    int n = idx / C4, c = idx % C4;
    int b = batch[n];
    float oe = 1.f + gin_eps[0];
    float4 hv = *(float4*)(h + (size_t)n * EMB + c * 4);
    float4 vv = *(const float4*)(vn_emb + c * 4);
    hv.x += vv.x; hv.y += vv.y; hv.z += vv.z; hv.w += vv.w;
    *(float4*)(h + (size_t)n * EMB + c * 4) = hv;
    float4 av = make_float4(hv.x * oe, hv.y * oe, hv.z * oe, hv.w * oe);
    *(float4*)(agg + (size_t)n * EMB + c * 4) = av;
    REDV4(pooled + (size_t)b * EMB + c * 4, hv.x, hv.y, hv.z, hv.w);
}

// ---------------- weight transpose + split (gin + vn weights) ----------------
__global__ void k_prep_w(const float* __restrict__ W1, const float* __restrict__ W2,
                         const float* __restrict__ V1, const float* __restrict__ V2,
                         __nv_bfloat16* __restrict__ w1h, __nv_bfloat16* __restrict__ w1l,
                         __nv_bfloat16* __restrict__ w2h, __nv_bfloat16* __restrict__ w2l,
                         __nv_bfloat16* __restrict__ v1h, __nv_bfloat16* __restrict__ v1l,
                         __nv_bfloat16* __restrict__ v2h, __nv_bfloat16* __restrict__ v2l) {
    const int SZ1 = NLAYERS * 2 * EMB * KP1;
    const int SZ2 = NLAYERS * EMB * KP2;
    const int SZ3 = (NLAYERS - 1) * 2 * EMB * KP1;
    const int SZ4 = (NLAYERS - 1) * EMB * KP2;
    int idx = blockIdx.x * blockDim.x + threadIdx.x;
    if (idx < SZ1) {
        int l = idx / (2 * EMB * KP1);
        int rem = idx % (2 * EMB * KP1);
        int n = rem / KP1, k = rem % KP1;
        float w = (k < EMB) ? W1[(size_t)l * EMB * 2 * EMB + (size_t)k * 2 * EMB + n] : 0.f;
        __nv_bfloat16 hi = __float2bfloat16(w);
        w1h[idx] = hi;
        w1l[idx] = __float2bfloat16(w - __bfloat162float(hi));
    } else if (idx < SZ1 + SZ2) {
        int j = idx - SZ1;
        int l = j / (EMB * KP2);
        int rem = j % (EMB * KP2);
        int n = rem / KP2, k = rem % KP2;
        float w = (k < 2 * EMB) ? W2[(size_t)l * 2 * EMB * EMB + (size_t)k * EMB + n] : 0.f;
        __nv_bfloat16 hi = __float2bfloat16(w);
        w2h[j] = hi;
        w2l[j] = __float2bfloat16(w - __bfloat162float(hi));
    } else if (idx < SZ1 + SZ2 + SZ3) {
        int j = idx - SZ1 - SZ2;
        int l = j / (2 * EMB * KP1);
        int rem = j % (2 * EMB * KP1);
        int n = rem / KP1, k = rem % KP1;
        float w = (k < EMB) ? V1[(size_t)l * EMB * 2 * EMB + (size_t)k * 2 * EMB + n] : 0.f;
        __nv_bfloat16 hi = __float2bfloat16(w);
        v1h[j] = hi;
        v1l[j] = __float2bfloat16(w - __bfloat162float(hi));
    } else if (idx < SZ1 + SZ2 + SZ3 + SZ4) {
        int j = idx - SZ1 - SZ2 - SZ3;
        int l = j / (EMB * KP2);
        int rem = j % (EMB * KP2);
        int n = rem / KP2, k = rem % KP2;
        float w = (k < 2 * EMB) ? V2[(size_t)l * 2 * EMB * EMB + (size_t)k * EMB + n] : 0.f;
        __nv_bfloat16 hi = __float2bfloat16(w);
        v2h[j] = hi;
        v2l[j] = __float2bfloat16(w - __bfloat162float(hi));
    }
}

// ---------------- fp32 [N,EMB] -> bf16 hi/lo [N,KP1], vectorized x4 ----------------
__global__ void k_split(const float* __restrict__ src, __nv_bfloat16* __restrict__ dh,
                        __nv_bfloat16* __restrict__ dl, int N) {
    int idx = blockIdx.x * blockDim.x + threadIdx.x;
    if (idx >= N * (KP1 / 4)) return;
    int n = idx / (KP1 / 4), k4 = (idx % (KP1 / 4)) * 4;
    float4 v = make_float4(0.f, 0.f, 0.f, 0.f);
    if (k4 < EMB) v = *(const float4*)(src + (size_t)n * EMB + k4);
    __nv_bfloat16 h0 = __float2bfloat16(v.x), h1 = __float2bfloat16(v.y);
    __nv_bfloat16 h2 = __float2bfloat16(v.z), h3 = __float2bfloat16(v.w);
    __nv_bfloat162 hp0, hp1, lp0, lp1;
    hp0.x = h0; hp0.y = h1; hp1.x = h2; hp1.y = h3;
    lp0.x = __float2bfloat16(v.x - __bfloat162float(h0));
    lp0.y = __float2bfloat16(v.y - __bfloat162float(h1));
    lp1.x = __float2bfloat16(v.z - __bfloat162float(h2));
    lp1.y = __float2bfloat16(v.w - __bfloat162float(h3));
    uint2 hw, lw;
    hw.x = *(uint32_t*)&hp0; hw.y = *(uint32_t*)&hp1;
    lw.x = *(uint32_t*)&lp0; lw.y = *(uint32_t*)&lp1;
    *(uint2*)(dh + (size_t)n * KP1 + k4) = hw;
    *(uint2*)(dl + (size_t)n * KP1 + k4) = lw;
}

// ---------------- edge scatter (vector atomics) ----------------
__global__ void k_edge_scatter(const float* __restrict__ h, float* __restrict__ agg,
                               const int* __restrict__ ei, const int* __restrict__ ea,
                               const float* __restrict__ bond_emb, int E) {
    int idx = blockIdx.x * blockDim.x + threadIdx.x;
    if (idx >= E * C4) return;
    int e = idx / C4, c = idx % C4;
    int row = ei[e];
    int col = ei[E + e];
    int a0 = ea[e * 3 + 0], a1 = ea[e * 3 + 1], a2 = ea[e * 3 + 2];
    float4 hv = *(const float4*)(h + (size_t)row * EMB + c * 4);
    float4 b0 = *(const float4*)(bond_emb + (size_t)(0 * BOND_V + a0) * EMB + c * 4);
    float4 b1 = *(const float4*)(bond_emb + (size_t)(1 * BOND_V + a1) * EMB + c * 4);
    float4 b2 = *(const float4*)(bond_emb + (size_t)(2 * BOND_V + a2) * EMB + c * 4);
    float mx = fmaxf(hv.x + b0.x + b1.x + b2.x, 0.f);
    float my = fmaxf(hv.y + b0.y + b1.y + b2.y, 0.f);
    float mz = fmaxf(hv.z + b0.z + b1.z + b2.z, 0.f);
    float mw = fmaxf(hv.w + b0.w + b1.w + b2.w, 0.f);
    REDV4(agg + (size_t)col * EMB + c * 4, mx, my, mz, mw);
}

// ================= bf16-split tensor-core GEMM, 256x128x32, 512 thr, cp.async 2-stage =======
// warp tile 64x32 (4x4 warp grid). FLOP/smem-byte = 33 -> crossbar at half capacity.
// mode 0: fp32 bn(+relu) -> out_f32
// mode 1: bf16 hi/lo split -> out_hi/out_lo (stride ldo, pads zeroed)
// mode 2: fp32 bn(+relu) -> out_f32 AND out_f32b
// mode 3: fused GIN epilogue: h = bn+relu + vn_next[batch]; agg=(1+eps)h; pooled += h
#define MM_BM 256
#define MM_BN 128
#define MM_BK 32
#define ROWB  80
#define SA_H  0
#define SA_L  20480
#define SB_H  40960
#define SB_L  51200
#define STAGE 61440
#define EPI_SC 122880
#define EPI_OF 123392
#define SMEM_TOT 123904

__global__ void __launch_bounds__(512, 1)
k_mma_gemm(const __nv_bfloat16* __restrict__ Ah, const __nv_bfloat16* __restrict__ Al,
           const __nv_bfloat16* __restrict__ Bh, const __nv_bfloat16* __restrict__ Bl,
           const float* __restrict__ bias,
           const float* __restrict__ bng, const float* __restrict__ bnb,
           const float* __restrict__ bnm, const float* __restrict__ bnv,
           float* __restrict__ out_f32, float* __restrict__ out_f32b,
           __nv_bfloat16* __restrict__ out_hi, __nv_bfloat16* __restrict__ out_lo,
           const int* __restrict__ batch, const float* __restrict__ vnp,
           float* __restrict__ pooledp, const float* __restrict__ epsp,
           int M, int Kpad, int Nc, int ldo, int do_relu, int mode) {
    extern __shared__ char sm[];
    const uint32_t smb = smem_u32(sm);
    const int tid = threadIdx.x;
    const int lane = tid & 31;
    const int warp = tid >> 5;          // 0..15
    const int warp_m = warp & 3;        // 64 rows each
    const int warp_n = warp >> 2;       // 0..3, 32 cols each
    const int row0 = blockIdx.y * MM_BM;
    const int col0 = blockIdx.x * MM_BN;

    float* scp = (float*)(sm + EPI_SC);
    float* ofp = (float*)(sm + EPI_OF);
    if (tid < MM_BN) {
        int gn = col0 + tid;
        float s = 0.f, o = 0.f;
        if (gn < Nc) {
            s = bng[gn] * rsqrtf(bnv[gn] + BN_EPS);
            o = bias[gn] * s + bnb[gn] - bnm[gn] * s;
        }
        scp[tid] = s;
        ofp[tid] = o;
    }

    float acc[4][4][4];
#pragma unroll
    for (int mi = 0; mi < 4; mi++)
#pragma unroll
        for (int nj = 0; nj < 4; nj++)
#pragma unroll
            for (int q = 0; q < 4; q++) acc[mi][nj][q] = 0.f;

    // staging: A 256 rows x 4 segs (16B): 1024 xfers, 2/thread; B 128 rows: 512, 1/thread
    const int r0i = tid >> 2, s0i = tid & 3;   // rows 0..127
    const int r1i = r0i + 128;                 // rows 128..255
    const int gmA0 = row0 + r0i, gmA1 = row0 + r1i;
    const int gnB0 = col0 + r0i;               // r0i < 128 = MM_BN
    const uint32_t szA0 = (gmA0 < M) ? 16u : 0u, szA1 = (gmA1 < M) ? 16u : 0u;
    const uint32_t szB0 = (gnB0 < Nc) ? 16u : 0u;
    const size_t oA0 = (size_t)min(gmA0, M - 1) * Kpad + s0i * 8;
    const size_t oA1 = (size_t)min(gmA1, M - 1) * Kpad + s0i * 8;
    const size_t oB0 = (size_t)min(gnB0, Nc - 1) * Kpad + s0i * 8;
    const uint32_t dA0 = r0i * ROWB + s0i * 16;
    const uint32_t dA1 = r1i * ROWB + s0i * 16;

#define ISSUE(ch, st) do { \
    const int _k0 = (ch) * MM_BK; \
    const uint32_t _sb = smb + (st) * STAGE; \
    CP_ASYNC16(_sb + SA_H + dA0, Ah + oA0 + _k0, szA0); \
    CP_ASYNC16(_sb + SA_H + dA1, Ah + oA1 + _k0, szA1); \
    CP_ASYNC16(_sb + SA_L + dA0, Al + oA0 + _k0, szA0); \
    CP_ASYNC16(_sb + SA_L + dA1, Al + oA1 + _k0, szA1); \
    CP_ASYNC16(_sb + SB_H + dA0, Bh + oB0 + _k0, szB0); \
    CP_ASYNC16(_sb + SB_L + dA0, Bl + oB0 + _k0, szB0); \
    CP_COMMIT(); \
} while (0)

    // ldmatrix lane addressing (bytes within array)
    const uint32_t aoff = (warp_m * 64 + (lane & 15)) * ROWB + (lane >> 4) * 16;
    const uint32_t boff = (warp_n * 32 + (lane & 7) + ((lane >> 4) << 3)) * ROWB
                        + ((lane >> 3) & 1) * 16;

    const int nk = Kpad / MM_BK;
    ISSUE(0, 0);
    for (int ch = 0; ch < nk; ch++) {
        const int st = ch & 1;
        CP_WAIT0();
        __syncthreads();                     // single barrier per chunk (see R14)
        if (ch + 1 < nk) ISSUE(ch + 1, st ^ 1);

        const uint32_t a_h = smb + st * STAGE + SA_H;
        const uint32_t a_l = smb + st * STAGE + SA_L;
        const uint32_t b_h = smb + st * STAGE + SB_H;
        const uint32_t b_l = smb + st * STAGE + SB_L;
#pragma unroll
        for (int ks = 0; ks < 2; ks++) {
            const uint32_t ka = ks * 32;
            uint32_t ah[4][4], al[4][4];
#pragma unroll
            for (int mi = 0; mi < 4; mi++) {
                LDSM4(ah[mi], a_h + aoff + mi * 16 * ROWB + ka);
                LDSM4(al[mi], a_l + aoff + mi * 16 * ROWB + ka);
            }
            uint32_t bh[2][4], bl[2][4];
            LDSM4(bh[0], b_h + boff + ka);
            LDSM4(bh[1], b_h + boff + 16 * ROWB + ka);
            LDSM4(bl[0], b_l + boff + ka);
            LDSM4(bl[1], b_l + boff + 16 * ROWB + ka);
            // b fragment for nj: nj0->bh[0]+0, nj1->bh[0]+2, nj2->bh[1]+0, nj3->bh[1]+2
#define COMBO(AF, BF) \
            { \
                _Pragma("unroll") \
                for (int mi = 0; mi < 4; mi++) { \
                    MMA16816(acc[mi][0], AF[mi], (BF[0] + 0)); \
                    MMA16816(acc[mi][1], AF[mi], (BF[0] + 2)); \
                    MMA16816(acc[mi][2], AF[mi], (BF[1] + 0)); \
                    MMA16816(acc[mi][3], AF[mi], (BF[1] + 2)); \
                } \
            }
            COMBO(ah, bh)
            COMBO(ah, bl)
            COMBO(al, bh)
#undef COMBO
        }
    }

    // ---- epilogue ----
    const int tg = lane >> 2;
    const int np = (lane & 3) * 2;
    const float oe = (mode == 3) ? (1.f + __ldg(epsp)) : 0.f;
#pragma unroll
    for (int mi = 0; mi < 4; mi++) {
        const int rb = row0 + warp_m * 64 + mi * 16 + tg;
        int bA = 0, bB = 0;
        if (mode == 3) {
            bA = (rb < M) ? batch[rb] : 0;
            bB = (rb + 8 < M) ? batch[rb + 8] : 0;
        }
#pragma unroll
        for (int nj = 0; nj < 4; nj++) {
            int ci = warp_n * 32 + nj * 8 + np;   // 0..127
            int gn = col0 + ci;
            float s0 = scp[ci], s1 = scp[ci + 1];
            float o0 = ofp[ci], o1 = ofp[ci + 1];
#pragma unroll
            for (int hb = 0; hb < 2; hb++) {
                int r = rb + hb * 8;
                if (r >= M) continue;
                float v0 = acc[mi][nj][hb * 2 + 0] * s0 + o0;
                float v1 = acc[mi][nj][hb * 2 + 1] * s1 + o1;
                if (do_relu) { v0 = fmaxf(v0, 0.f); v1 = fmaxf(v1, 0.f); }
                if (mode == 1) {
                    if (gn < ldo) {
                        __nv_bfloat16 h0 = __float2bfloat16(v0);
                        __nv_bfloat16 h1 = __float2bfloat16(v1);
                        __nv_bfloat162 hp; hp.x = h0; hp.y = h1;
                        __nv_bfloat162 lp;
                        lp.x = __float2bfloat16(v0 - __bfloat162float(h0));
                        lp.y = __float2bfloat16(v1 - __bfloat162float(h1));
                        *(__nv_bfloat162*)(out_hi + (size_t)r * ldo + gn) = hp;
                        *(__nv_bfloat162*)(out_lo + (size_t)r * ldo + gn) = lp;
                    }
                } else if (mode == 3) {
                    if (gn < Nc) {
                        int b = hb ? bB : bA;
                        float2 vv = *(const float2*)(vnp + (size_t)b * EMB + gn);
                        float h0 = v0 + vv.x;
                        float h1 = v1 + vv.y;
                        float2 hw; hw.x = h0; hw.y = h1;
                        *(float2*)(out_f32 + (size_t)r * Nc + gn) = hw;
                        float2 aw; aw.x = h0 * oe; aw.y = h1 * oe;
                        *(float2*)(out_f32b + (size_t)r * Nc + gn) = aw;
                        REDV2(pooledp + (size_t)b * EMB + gn, h0, h1);
                    }
                } else {
                    if (gn < Nc) {
                        float2 fv; fv.x = v0; fv.y = v1;
                        *(float2*)(out_f32 + (size_t)r * Nc + gn) = fv;
                        if (mode == 2)
                            *(float2*)(out_f32b + (size_t)r * Nc + gn) = fv;
                    }
                }
            }
        }
    }
}

// ---------------- final mean pool ----------------
__global__ void k_final_zero(float* __restrict__ out, float* __restrict__ counts) {
    int idx = blockIdx.x * blockDim.x + threadIdx.x;
    if (idx < NGRAPH * EMB) out[idx] = 0.f;
    if (idx < NGRAPH) counts[idx] = 0.f;
}
__global__ void k_final_acc(const float* __restrict__ h, const int* __restrict__ batch,
                            float* __restrict__ out, float* __restrict__ counts, int N) {
    int idx = blockIdx.x * blockDim.x + threadIdx.x;
    if (idx >= N * C4) return;
    int n = idx / C4, c = idx % C4;
    int b = batch[n];
    float4 hv = *(const float4*)(h + (size_t)n * EMB + c * 4);
    REDV4(out + (size_t)b * EMB + c * 4, hv.x, hv.y, hv.z, hv.w);
    if (c == 0) atomicAdd(counts + b, 1.f);
}
__global__ void k_final_div(float* __restrict__ out, const float* __restrict__ counts) {
    int idx = blockIdx.x * blockDim.x + threadIdx.x;
    if (idx >= NGRAPH * EMB) return;
    int g = idx / EMB;
    out[idx] /= fmaxf(counts[g], 1.f);
}

static inline dim3 mma_grid(int M, int Nc) {
    return dim3((Nc + MM_BN - 1) / MM_BN, (M + MM_BM - 1) / MM_BM);
}

extern "C" void kernel_launch(void* const* d_in, const int* in_sizes, int n_in,
                              void* d_out, int out_size) {
    const int*   x        = (const int*)  d_in[0];
    const int*   ei       = (const int*)  d_in[1];
    const int*   ea       = (const int*)  d_in[2];
    const int*   batch    = (const int*)  d_in[3];
    const float* atom_emb = (const float*)d_in[4];
    const float* bond_emb = (const float*)d_in[5];
    const float* vn_emb   = (const float*)d_in[6];
    const float* gin_eps  = (const float*)d_in[7];
    const float* gin_W1   = (const float*)d_in[8];
    const float* gin_b1   = (const float*)d_in[9];
    const float* gin_bn1_g= (const float*)d_in[10];
    const float* gin_bn1_b= (const float*)d_in[11];
    const float* gin_bn1_m= (const float*)d_in[12];
    const float* gin_bn1_v= (const float*)d_in[13];
    const float* gin_W2   = (const float*)d_in[14];
    const float* gin_b2   = (const float*)d_in[15];
    const float* bn_g     = (const float*)d_in[16];
    const float* bn_b     = (const float*)d_in[17];
    const float* bn_m     = (const float*)d_in[18];
    const float* bn_v     = (const float*)d_in[19];
    const float* vn_W1    = (const float*)d_in[20];
    const float* vn_b1    = (const float*)d_in[21];
    const float* vn_bn1_g = (const float*)d_in[22];
    const float* vn_bn1_b = (const float*)d_in[23];
    const float* vn_bn1_m = (const float*)d_in[24];
    const float* vn_bn1_v = (const float*)d_in[25];
    const float* vn_W2    = (const float*)d_in[26];
    const float* vn_b2    = (const float*)d_in[27];
    const float* vn_bn2_g = (const float*)d_in[28];
    const float* vn_bn2_b = (const float*)d_in[29];
    const float* vn_bn2_m = (const float*)d_in[30];
    const float* vn_bn2_v = (const float*)d_in[31];

    const int N = in_sizes[0] / ATOM_F;
    const int E = in_sizes[1] / 2;
    float* out = (float*)d_out;

    float *h, *agg, *vn, *pooled, *counts;
    __nv_bfloat16 *aggh, *aggl, *t1h, *t1l, *plh, *pll, *vnth, *vntl;
    __nv_bfloat16 *w1h, *w1l, *w2h, *w2l, *v1h, *v1l, *v2h, *v2l;
    cudaGetSymbolAddress((void**)&h,      g_h);
    cudaGetSymbolAddress((void**)&agg,    g_agg);
    cudaGetSymbolAddress((void**)&vn,     g_vn);
    cudaGetSymbolAddress((void**)&pooled, g_pooled);
    cudaGetSymbolAddress((void**)&counts, g_counts);
    cudaGetSymbolAddress((void**)&aggh,   g_agg_h);
    cudaGetSymbolAddress((void**)&aggl,   g_agg_l);
    cudaGetSymbolAddress((void**)&t1h,    g_t1_h);
    cudaGetSymbolAddress((void**)&t1l,    g_t1_l);
    cudaGetSymbolAddress((void**)&plh,    g_pl_h);
    cudaGetSymbolAddress((void**)&pll,    g_pl_l);
    cudaGetSymbolAddress((void**)&vnth,   g_vnt_h);
    cudaGetSymbolAddress((void**)&vntl,   g_vnt_l);
    cudaGetSymbolAddress((void**)&w1h,    g_w1t_h);
    cudaGetSymbolAddress((void**)&w1l,    g_w1t_l);
    cudaGetSymbolAddress((void**)&w2h,    g_w2t_h);
    cudaGetSymbolAddress((void**)&w2l,    g_w2t_l);
    cudaGetSymbolAddress((void**)&v1h,    g_wv1_h);
    cudaGetSymbolAddress((void**)&v1l,    g_wv1_l);
    cudaGetSymbolAddress((void**)&v2h,    g_wv2_h);
    cudaGetSymbolAddress((void**)&v2l,    g_wv2_l);

    cudaFuncSetAttribute(k_mma_gemm, cudaFuncAttributeMaxDynamicSharedMemorySize, SMEM_TOT);

    const int T = 256;
    const int gN  = (N * C4 + T - 1) / T;
    const int gE  = (E * C4 + T - 1) / T;
    const int gVN = (NGRAPH * EMB + T - 1) / T;
    const int gS  = (N * (KP1 / 4) + T - 1) / T;
    const int gSP = (NGRAPH * (KP1 / 4) + T - 1) / T;
    const int WTOT = NLAYERS * 2 * EMB * KP1 + NLAYERS * EMB * KP2
                   + (NLAYERS - 1) * 2 * EMB * KP1 + (NLAYERS - 1) * EMB * KP2;

    // launch order keeps k_edge_scatter at index 3 (ncu slot)
    k_atom_encode<<<gN, T>>>(x, atom_emb, h, N);                       // 0
    k_vn_init<<<gVN, T>>>(vn_emb, vn, pooled);                         // 1
    k_vnadd0<<<gN, T>>>(h, agg, vn_emb, batch, pooled, gin_eps, N);    // 2

    for (int l = 0; l < NLAYERS; l++) {
        const int do_pool = (l < NLAYERS - 1);
        k_edge_scatter<<<gE, T>>>(h, agg, ei, ea, bond_emb, E);        // l=0: 3
        if (l == 0)
            k_prep_w<<<(WTOT + T - 1) / T, T>>>(gin_W1, gin_W2, vn_W1, vn_W2,
                                                w1h, w1l, w2h, w2l, v1h, v1l, v2h, v2l);
        k_split<<<gS, T>>>(agg, aggh, aggl, N);
        // GEMM1: t1(hi/lo) = relu(bn1(agg @ W1 + b1))
        k_mma_gemm<<<mma_grid(N, 2 * EMB), 512, SMEM_TOT>>>(
            aggh, aggl, w1h + (size_t)l * 2 * EMB * KP1, w1l + (size_t)l * 2 * EMB * KP1,
            gin_b1 + l * 2 * EMB,
            gin_bn1_g + l * 2 * EMB, gin_bn1_b + l * 2 * EMB,
            gin_bn1_m + l * 2 * EMB, gin_bn1_v + l * 2 * EMB,
            nullptr, nullptr, t1h, t1l, nullptr, nullptr, nullptr, nullptr,
            N, KP1, 2 * EMB, KP2, 1, 1);
        if (do_pool) {
            // vn MLP (produces vn_{l+1}; mode 2 also resets pooled = vn_{l+1})
            k_split<<<gSP, T>>>(pooled, plh, pll, NGRAPH);
            k_mma_gemm<<<mma_grid(NGRAPH, 2 * EMB), 512, SMEM_TOT>>>(
                plh, pll, v1h + (size_t)l * 2 * EMB * KP1, v1l + (size_t)l * 2 * EMB * KP1,
                vn_b1 + l * 2 * EMB,
                vn_bn1_g + l * 2 * EMB, vn_bn1_b + l * 2 * EMB,
                vn_bn1_m + l * 2 * EMB, vn_bn1_v + l * 2 * EMB,
                nullptr, nullptr, vnth, vntl, nullptr, nullptr, nullptr, nullptr,
                NGRAPH, KP1, 2 * EMB, KP2, 1, 1);
            k_mma_gemm<<<mma_grid(NGRAPH, EMB), 512, SMEM_TOT>>>(
                vnth, vntl, v2h + (size_t)l * EMB * KP2, v2l + (size_t)l * EMB * KP2,
                vn_b2 + l * EMB,
                vn_bn2_g + l * EMB, vn_bn2_b + l * EMB,
                vn_bn2_m + l * EMB, vn_bn2_v + l * EMB,
                vn, pooled, nullptr, nullptr, nullptr, nullptr, nullptr, nullptr,
                NGRAPH, KP2, EMB, EMB, 1, 2);
            // GEMM2 fused (mode 3)
            k_mma_gemm<<<mma_grid(N, EMB), 512, SMEM_TOT>>>(
                t1h, t1l, w2h + (size_t)l * EMB * KP2, w2l + (size_t)l * EMB * KP2,
                gin_b2 + l * EMB,
                bn_g + l * EMB, bn_b + l * EMB, bn_m + l * EMB, bn_v + l * EMB,
                h, agg, nullptr, nullptr, batch, vn, pooled, gin_eps + (l + 1),
                N, KP2, EMB, EMB, 1, 3);
        } else {
            // last layer: plain h = bn(t1@W2+b2), no relu
            k_mma_gemm<<<mma_grid(N, EMB), 512, SMEM_TOT>>>(
                t1h, t1l, w2h + (size_t)l * EMB * KP2, w2l + (size_t)l * EMB * KP2,
                gin_b2 + l * EMB,
                bn_g + l * EMB, bn_b + l * EMB, bn_m + l * EMB, bn_v + l * EMB,
                h, nullptr, nullptr, nullptr, nullptr, nullptr, nullptr, nullptr,
                N, KP2, EMB, EMB, 0, 0);
        }
    }

    k_final_zero<<<gVN, T>>>(out, counts);
    k_final_acc<<<gN, T>>>(h, batch, out, counts, N);
    k_final_div<<<gVN, T>>>(out, counts);
}